// round 2
// baseline (speedup 1.0000x reference)
#include <cuda_runtime.h>
#include <math.h>

#define Bsz    4
#define Cdim   128
#define Lseq   4096
#define Dd     32
#define DI     64
#define DS     16
#define NPROJ  34
#define SEQ    16
#define NC     64
#define TC     64
#define EPSf   1e-5f

// ---------------- scratch (device globals; no allocation allowed) ----------------
__device__ float g_xn2 [SEQ*Lseq*Dd];       // post double-LN, per (split,b)
__device__ float g_xz  [SEQ*Lseq*2*DI];     // in_proj output (xc_pre | z)
__device__ float g_xc  [SEQ*Lseq*DI];       // conv+silu output
__device__ float g_proj[SEQ*Lseq*NPROJ];    // x_proj output (dtr|B|C)
__device__ float g_dt  [SEQ*Lseq*DI];       // softplus dt
__device__ float g_P   [SEQ*NC*DI*DS];      // chunk A-products
__device__ float g_Q   [SEQ*NC*DI*DS];      // chunk local scans
__device__ float g_hin [SEQ*NC*DI*DS];      // chunk initial states
__device__ float g_ym  [SEQ*Lseq*DI];       // gated scan output
__device__ float g_zc  [Bsz*Lseq*Cdim];     // concatenated split outputs
__device__ float g_pwt [Cdim*Cdim];         // transposed final proj weight

__device__ __forceinline__ float wsum(float v){
    #pragma unroll
    for(int o=16;o;o>>=1) v += __shfl_xor_sync(0xffffffffu, v, o);
    return v;
}
__device__ __forceinline__ float siluf(float x){ return x/(1.f+__expf(-x)); }

// ---------------- K0: transpose final projection weight ----------------
__global__ void k_tr(const float* __restrict__ pw){
    int i = blockIdx.x*256 + threadIdx.x;      // 16384
    int o = i>>7, c = i&127;
    g_pwt[c*128+o] = pw[i];
}

// ---------------- K1: LN over C, then per-split LN over D ----------------
__global__ void k_ln(const float* __restrict__ x, const float* __restrict__ lg,
                     const float* __restrict__ lb, const float* __restrict__ pg,
                     const float* __restrict__ pb){
    __shared__ float sx[128][33];
    int b = blockIdx.y, l0 = blockIdx.x*32, tid = threadIdx.x;
    for(int i=tid;i<128*32;i+=256){
        int c=i>>5, li=i&31;
        sx[c][li] = x[(b*128 + c)*Lseq + l0 + li];
    }
    __syncthreads();
    int w = tid>>5, lane = tid&31;
    for(int lc=w; lc<32; lc+=8){
        float v0=sx[lane][lc], v1=sx[lane+32][lc], v2=sx[lane+64][lc], v3=sx[lane+96][lc];
        float mu = wsum(v0+v1+v2+v3)*(1.f/128.f);
        float d0=v0-mu,d1=v1-mu,d2=v2-mu,d3=v3-mu;
        float rs = rsqrtf(wsum(d0*d0+d1*d1+d2*d2+d3*d3)*(1.f/128.f)+EPSf);
        float xn[4];
        xn[0]=d0*rs*lg[lane     ]+lb[lane     ];
        xn[1]=d1*rs*lg[lane+ 32]+lb[lane+ 32];
        xn[2]=d2*rs*lg[lane+ 64]+lb[lane+ 64];
        xn[3]=d3*rs*lg[lane+ 96]+lb[lane+ 96];
        #pragma unroll
        for(int g=0; g<4; g++){
            float mu2 = wsum(xn[g])*(1.f/32.f);
            float dd  = xn[g]-mu2;
            float rs2 = rsqrtf(wsum(dd*dd)*(1.f/32.f)+EPSf);
            float o = dd*rs2*pg[g*32+lane] + pb[g*32+lane];
            g_xn2[((g*Bsz + b)*Lseq + l0+lc)*Dd + lane] = o;
        }
    }
}

// ---------------- K2: in_proj GEMM (32 -> 128) ----------------
__global__ void k_inproj(const float* __restrict__ W){
    __shared__ float sW[32*128];
    __shared__ float sx[32*32];
    int seq=blockIdx.y, l0=blockIdx.x*32, g=seq>>2, tid=threadIdx.x;
    for(int i=tid;i<4096;i+=128) sW[i] = W[g*4096+i];
    for(int i=tid;i<1024;i+=128) sx[i] = g_xn2[(seq*Lseq+l0)*32 + i];
    __syncthreads();
    float acc[32];
    #pragma unroll
    for(int t=0;t<32;t++) acc[t]=0.f;
    int n = tid;
    #pragma unroll 4
    for(int k=0;k<32;k++){
        float w = sW[k*128+n];
        #pragma unroll
        for(int t=0;t<32;t++) acc[t] = fmaf(sx[t*32+k], w, acc[t]);
    }
    #pragma unroll
    for(int t=0;t<32;t++) g_xz[(seq*Lseq+l0+t)*128 + n] = acc[t];
}

// ---------------- K3: causal conv(4) + bias + SiLU ----------------
__global__ void k_conv(const float* __restrict__ cw, const float* __restrict__ cb){
    int idx = blockIdx.x*256 + threadIdx.x;     // SEQ*L*DI = 2^22
    int ch = idx & 63; int t = (idx>>6) & (Lseq-1); int seq = idx >> 18;
    int g = seq>>2;
    float acc = cb[g*64+ch];
    const float* cwp = cw + g*256 + ch*4;
    #pragma unroll
    for(int k=0;k<4;k++){
        int tt = t-3+k;
        if(tt>=0) acc = fmaf(g_xz[(seq*Lseq+tt)*128 + ch], cwp[k], acc);
    }
    g_xc[idx] = siluf(acc);
}

// ---------------- K4: x_proj GEMM (64 -> 34) ----------------
__global__ void k_xproj(const float* __restrict__ W){
    __shared__ float sW[64*NPROJ];
    __shared__ float sx[32*64];
    int seq=blockIdx.y, l0=blockIdx.x*32, g=seq>>2, tid=threadIdx.x;
    for(int i=tid;i<64*NPROJ;i+=64) sW[i] = W[g*64*NPROJ + i];
    for(int i=tid;i<2048;i+=64)     sx[i] = g_xc[(seq*Lseq+l0)*64 + i];
    __syncthreads();
    if(tid < NPROJ){
        float acc[32];
        #pragma unroll
        for(int t=0;t<32;t++) acc[t]=0.f;
        #pragma unroll 4
        for(int k=0;k<64;k++){
            float w = sW[k*NPROJ + tid];
            #pragma unroll
            for(int t=0;t<32;t++) acc[t] = fmaf(sx[t*64+k], w, acc[t]);
        }
        #pragma unroll
        for(int t=0;t<32;t++) g_proj[(seq*Lseq+l0+t)*NPROJ + tid] = acc[t];
    }
}

// ---------------- K5: dt = softplus(proj[:2] @ dtw + dtb) ----------------
__global__ void k_dt(const float* __restrict__ dtw, const float* __restrict__ dtb){
    int idx = blockIdx.x*256 + threadIdx.x;     // SEQ*L*DI
    int d = idx & 63; int t = (idx>>6) & (Lseq-1); int seq = idx >> 18; int g = seq>>2;
    const float* pr = &g_proj[(seq*Lseq+t)*NPROJ];
    float v = fmaf(pr[0], dtw[g*128 + d], fmaf(pr[1], dtw[g*128 + 64 + d], dtb[g*64+d]));
    g_dt[idx] = (v > 20.f) ? v : log1pf(__expf(v));
}

// ---------------- K6: scan phase 1 — per-chunk (P, Q) ----------------
__global__ void k_scan1(const float* __restrict__ A_log){
    __shared__ float s_dt[16*64], s_xc[16*64], s_bc[16*16];
    int seq=blockIdx.y, ck=blockIdx.x, g=seq>>2, d=threadIdx.x;
    float A[DS], P[DS], Q[DS];
    #pragma unroll
    for(int s=0;s<DS;s++){ A[s] = -__expf(A_log[(g*64+d)*16+s]); P[s]=1.f; Q[s]=0.f; }
    int tbase = ck*TC;
    for(int sub=0; sub<TC/16; sub++){
        int tb = tbase + sub*16;
        __syncthreads();
        for(int i=d;i<1024;i+=64){
            s_dt[i]=g_dt[(seq*Lseq+tb)*64 + i];
            s_xc[i]=g_xc[(seq*Lseq+tb)*64 + i];
        }
        for(int i=d;i<256;i+=64){
            int t=i>>4, s=i&15;
            s_bc[i] = g_proj[(seq*Lseq+tb+t)*NPROJ + 2 + s];
        }
        __syncthreads();
        #pragma unroll 4
        for(int i=0;i<16;i++){
            float dtv = s_dt[i*64+d];
            float dx  = dtv * s_xc[i*64+d];
            #pragma unroll
            for(int s=0;s<DS;s++){
                float e = __expf(A[s]*dtv);
                Q[s] = fmaf(e, Q[s], dx*s_bc[i*16+s]);
                P[s] *= e;
            }
        }
    }
    int base = ((seq*NC+ck)*64 + d)*16;
    #pragma unroll
    for(int s=0;s<16;s+=4){
        *(float4*)&g_P[base+s] = make_float4(P[s],P[s+1],P[s+2],P[s+3]);
        *(float4*)&g_Q[base+s] = make_float4(Q[s],Q[s+1],Q[s+2],Q[s+3]);
    }
}

// ---------------- K7: scan phase 2 — sequential across chunks ----------------
__global__ void k_scan2(){
    int idx = blockIdx.x*256 + threadIdx.x;     // SEQ*1024
    int ds = idx & 1023; int seq = idx >> 10;
    float h = 0.f;
    int base = seq*NC*1024 + ds;
    #pragma unroll 4
    for(int c=0;c<NC;c++){
        g_hin[base + c*1024] = h;
        h = fmaf(g_P[base + c*1024], h, g_Q[base + c*1024]);
    }
}

// ---------------- K8: scan phase 3 — replay + y + gate fusion ----------------
__global__ void k_scan3(const float* __restrict__ A_log, const float* __restrict__ Dpar){
    __shared__ float s_dt[1024], s_xc[1024], s_z[1024], s_bc[256], s_cc[256];
    int seq=blockIdx.y, ck=blockIdx.x, g=seq>>2, d=threadIdx.x;
    float A[DS], h[DS];
    #pragma unroll
    for(int s=0;s<DS;s++) A[s] = -__expf(A_log[(g*64+d)*16+s]);
    int hb = ((seq*NC+ck)*64 + d)*16;
    #pragma unroll
    for(int s=0;s<16;s+=4){
        float4 v = *(const float4*)&g_hin[hb+s];
        h[s]=v.x; h[s+1]=v.y; h[s+2]=v.z; h[s+3]=v.w;
    }
    float Dp = Dpar[g*64+d];
    int tbase = ck*TC;
    for(int sub=0; sub<TC/16; sub++){
        int tb = tbase + sub*16;
        __syncthreads();
        for(int i=d;i<1024;i+=64){
            s_dt[i]=g_dt[(seq*Lseq+tb)*64 + i];
            s_xc[i]=g_xc[(seq*Lseq+tb)*64 + i];
            int t=i>>6, dd=i&63;
            s_z[i] = g_xz[(seq*Lseq+tb+t)*128 + 64 + dd];
        }
        for(int i=d;i<256;i+=64){
            int t=i>>4, s=i&15;
            s_bc[i] = g_proj[(seq*Lseq+tb+t)*NPROJ + 2  + s];
            s_cc[i] = g_proj[(seq*Lseq+tb+t)*NPROJ + 18 + s];
        }
        __syncthreads();
        #pragma unroll 4
        for(int i=0;i<16;i++){
            float dtv = s_dt[i*64+d];
            float xcv = s_xc[i*64+d];
            float dx  = dtv*xcv;
            float y = 0.f;
            #pragma unroll
            for(int s=0;s<DS;s++){
                float e = __expf(A[s]*dtv);
                h[s] = fmaf(e, h[s], dx*s_bc[i*16+s]);
                y = fmaf(h[s], s_cc[i*16+s], y);
            }
            float zv = s_z[i*64+d];
            g_ym[(seq*Lseq+tb+i)*64 + d] = (y + Dp*xcv) * siluf(zv);
        }
    }
}

// ---------------- K9: out_proj(64->32) + skip + pvm_proj(32->32) ----------------
__global__ void k_out(const float* __restrict__ W1, const float* __restrict__ W2,
                      const float* __restrict__ pb2, const float* __restrict__ skipv){
    __shared__ float sW1[64*32], sW2[32*32], spb[32], su[8*32], sym[8*64];
    int seq=blockIdx.y, g=seq>>2, b=seq&3, t0=blockIdx.x*8, tid=threadIdx.x;
    for(int i=tid;i<2048;i+=256) sW1[i]=W1[g*2048+i];
    for(int i=tid;i<1024;i+=256) sW2[i]=W2[g*1024+i];
    if(tid<32) spb[tid]=pb2[g*32+tid];
    for(int i=tid;i<512;i+=256) sym[i]=g_ym[(seq*Lseq+t0)*64 + i];
    float skip = skipv[g];
    __syncthreads();
    int w = tid>>5, lane = tid&31;
    int t = t0 + w;
    float acc = 0.f;
    #pragma unroll 8
    for(int k=0;k<64;k++) acc = fmaf(sym[w*64+k], sW1[k*32+lane], acc);
    float u = acc + skip * g_xn2[(seq*Lseq+t)*32 + lane];
    su[w*32+lane] = u;
    __syncwarp();
    float acc2 = spb[lane];
    #pragma unroll 8
    for(int n=0;n<32;n++) acc2 = fmaf(su[w*32+n], sW2[n*32+lane], acc2);
    g_zc[(b*Lseq+t)*128 + g*32 + lane] = acc2;
}

// ---------------- K10: final proj (128x128) + BN + exact GELU ----------------
__global__ void k_final(const float* __restrict__ pb2, const float* __restrict__ bg,
                        const float* __restrict__ bb, const float* __restrict__ bm,
                        const float* __restrict__ bv, float* __restrict__ out){
    __shared__ float st[32*128];
    int b = blockIdx.y, l0 = blockIdx.x*32, o = threadIdx.x;
    for(int i=o;i<4096;i+=128) st[i] = g_zc[(b*Lseq+l0)*128 + i];
    float scale = bg[o]*rsqrtf(bv[o]+EPSf);
    float c0 = (pb2[o]-bm[o])*scale + bb[o];
    __syncthreads();
    float acc[32];
    #pragma unroll
    for(int t=0;t<32;t++) acc[t]=0.f;
    #pragma unroll 4
    for(int c=0;c<128;c++){
        float w = g_pwt[c*128+o];
        #pragma unroll
        for(int t=0;t<32;t++) acc[t] = fmaf(st[t*128+c], w, acc[t]);
    }
    __syncthreads();
    #pragma unroll
    for(int t=0;t<32;t++){
        float v = fmaf(acc[t], scale, c0);
        st[o*32+t] = 0.5f*v*(1.f + erff(v*0.70710678118654752f));
    }
    __syncthreads();
    for(int i=o;i<4096;i+=128){
        int oo = i>>5, li = i&31;
        out[(b*128+oo)*Lseq + l0 + li] = st[i];
    }
}

// ---------------- launch ----------------
extern "C" void kernel_launch(void* const* d_in, const int* in_sizes, int n_in,
                              void* d_out, int out_size){
    const float* x         = (const float*)d_in[0];
    const float* ln_g      = (const float*)d_in[1];
    const float* ln_b      = (const float*)d_in[2];
    const float* pvm_ln_g  = (const float*)d_in[3];
    const float* pvm_ln_b  = (const float*)d_in[4];
    const float* in_proj_w = (const float*)d_in[5];
    const float* conv_w    = (const float*)d_in[6];
    const float* conv_b    = (const float*)d_in[7];
    const float* x_proj_w  = (const float*)d_in[8];
    const float* dt_proj_w = (const float*)d_in[9];
    const float* dt_bias   = (const float*)d_in[10];
    const float* A_log     = (const float*)d_in[11];
    const float* D_param   = (const float*)d_in[12];
    const float* out_proj_w= (const float*)d_in[13];
    const float* skip_scale= (const float*)d_in[14];
    const float* pvm_proj_w= (const float*)d_in[15];
    const float* pvm_proj_b= (const float*)d_in[16];
    const float* proj_w    = (const float*)d_in[17];
    const float* proj_b    = (const float*)d_in[18];
    const float* bn_g      = (const float*)d_in[19];
    const float* bn_b      = (const float*)d_in[20];
    const float* bn_mean   = (const float*)d_in[21];
    const float* bn_var    = (const float*)d_in[22];
    float* out = (float*)d_out;

    k_tr    <<<64, 256>>>(proj_w);
    k_ln    <<<dim3(128,4), 256>>>(x, ln_g, ln_b, pvm_ln_g, pvm_ln_b);
    k_inproj<<<dim3(128,16), 128>>>(in_proj_w);
    k_conv  <<<16384, 256>>>(conv_w, conv_b);
    k_xproj <<<dim3(128,16), 64>>>(x_proj_w);
    k_dt    <<<16384, 256>>>(dt_proj_w, dt_bias);
    k_scan1 <<<dim3(64,16), 64>>>(A_log);
    k_scan2 <<<64, 256>>>();
    k_scan3 <<<dim3(64,16), 64>>>(A_log, D_param);
    k_out   <<<dim3(512,16), 256>>>(out_proj_w, pvm_proj_w, pvm_proj_b, skip_scale);
    k_final <<<dim3(128,4), 128>>>(proj_b, bn_g, bn_b, bn_mean, bn_var, out);
}